// round 14
// baseline (speedup 1.0000x reference)
#include <cuda_runtime.h>
#include <cstdint>

// Problem constants
#define T_STEPS  4096
#define NB       64          // batch
#define NI       128         // input dim
#define NH       1024        // hidden dim
#define KP       1152        // NH + NI (concatenated [h ; x] dot length)
#define GRID     128         // 32 j-blocks x 4 b-blocks (<= 148 SMs, 1 CTA/SM)
#define NTHREADS 512
#define NWARPS   16
#define WPAIRS   36          // (KP/2) / NWARPS : f32x2 pairs per warp-slice
#define BSUB     16          // batches per CTA
#define NJ       32          // output columns per CTA
#define SMEM_BYTES (BSUB * KP * 4 + NWARPS * BSUB * 32 * 8)  // 73728 + 65536 = 139264

// Persistent scratch (no allocation allowed): ping-pong hidden state
__device__ float    g_h[2][NB * NH];
__device__ unsigned g_bar_cnt = 0;
__device__ unsigned g_bar_gen = 0;

__device__ __forceinline__ void fma2(unsigned long long& d,
                                     unsigned long long a,
                                     unsigned long long b) {
    asm("fma.rn.f32x2 %0, %1, %2, %0;" : "+l"(d) : "l"(a), "l"(b));
}
__device__ __forceinline__ unsigned long long pack2(float x, float y) {
    unsigned long long v;
    asm("mov.b64 %0, {%1, %2};" : "=l"(v) : "f"(x), "f"(y));
    return v;
}
__device__ __forceinline__ float2 unpack2(unsigned long long v) {
    float2 f;
    asm("mov.b64 {%0, %1}, %2;" : "=f"(f.x), "=f"(f.y) : "l"(v));
    return f;
}

// Replay-safe grid barrier. Barrier i releases by setting g_bar_gen = expect
// (= i+1, values cycle 1..T each run; pre-release value is always != expect,
// counter self-resets, so CUDA-graph replays start clean). Spinners compare
// against a statically known target -> no load-before-atomic ordering hazard.
__device__ __forceinline__ void grid_barrier(unsigned expect) {
    __threadfence();           // publish this thread's global writes
    __syncthreads();
    if (threadIdx.x == 0) {
        unsigned a = atomicAdd(&g_bar_cnt, 1u);
        if (a == GRID - 1) {
            g_bar_cnt = 0;
            __threadfence();
            atomicExch(&g_bar_gen, expect);
        } else {
            volatile unsigned* gp = &g_bar_gen;
            while (*gp != expect) { __nanosleep(32); }
        }
    }
    __syncthreads();
}

__global__ void __launch_bounds__(NTHREADS, 1)
esn_kernel(const float* __restrict__ x,      // [T, B, I]
           const float* __restrict__ wih,    // [H, I]
           const float* __restrict__ whh,    // [H, H]
           const float* __restrict__ bih,    // [H]
           const float* __restrict__ bhh,    // [H]
           float* __restrict__ out)          // [B, H]
{
    extern __shared__ float smem[];
    float*  hx   = smem;                              // [BSUB][KP]  staged [h ; x_t]
    float2* part = (float2*)(smem + BSUB * KP);       // [NWARPS][BSUB][32] partials

    const int tid  = threadIdx.x;
    const int w    = tid >> 5;                        // warp id (= batch idx in reduce)
    const int lane = tid & 31;                        // = local j
    const int jb   = blockIdx.x & 31;                 // j-block
    const int bb   = blockIdx.x >> 5;                 // b-block
    const int j    = jb * NJ + lane;                  // this lane's output column
    const int b0   = bb * BSUB;

    // ---- persistent packed weights: warp w owns K'-pairs [w*36, w*36+36) ----
    // Concatenated weight row: [ Whh[j, 0..1023] ; Wih[j, 0..127] ]
    unsigned long long Wr[WPAIRS];
    {
        const int kbase = w * (2 * WPAIRS);           // = w*72 (even, no straddle)
        #pragma unroll
        for (int r = 0; r < WPAIRS; ++r) {
            const int k = kbase + 2 * r;
            float a, b;
            if (k < NH) { a = whh[j * NH + k];        b = whh[j * NH + k + 1]; }
            else        { a = wih[j * NI + (k - NH)]; b = wih[j * NI + (k - NH) + 1]; }
            Wr[r] = pack2(a, b);
        }
    }

    const float bias = bih[j] + bhh[j];
    const int   oidx = (b0 + w) * NH + j;   // output element owned in reduce phase

    // h_0 = 0 : each CTA zeros exactly its own output block (replay-safe)
    g_h[0][oidx] = 0.0f;

    for (int t = 0; t < T_STEPS; ++t) {
        grid_barrier((unsigned)(t + 1));     // makes h_t (or the zeros) visible

        // ---- stage h_t (L2, bypass stale L1 via ldcg) and x_t into smem ----
        const float* hsrc = g_h[t & 1] + b0 * NH;
        const float* xsrc = x + ((size_t)t * (NB * NI)) + b0 * NI;
        #pragma unroll
        for (int it = 0; it < 9; ++it) {     // 16*288 float4 = 18432 floats
            const int v  = tid + it * NTHREADS;
            const int b  = v / 288;
            const int c4 = v - b * 288;
            float4 val;
            if (c4 < 256) val = __ldcg(((const float4*)(hsrc + b * NH)) + c4);
            else          val = __ldg (((const float4*)(xsrc + b * NI)) + (c4 - 256));
            *(float4*)(hx + b * KP + c4 * 4) = val;
        }
        __syncthreads();

        // ---- partial dot products: f32x2 pairs over K', uniform LDS broadcast ----
        #pragma unroll 1
        for (int b = 0; b < BSUB; ++b) {
            const unsigned long long* hp =
                (const unsigned long long*)(hx + b * KP) + w * WPAIRS;
            unsigned long long a0 = 0ull, a1 = 0ull;   // two chains for ILP
            #pragma unroll
            for (int r = 0; r < WPAIRS; r += 2) {
                fma2(a0, hp[r],     Wr[r]);
                fma2(a1, hp[r + 1], Wr[r + 1]);
            }
            const float2 s0 = unpack2(a0);
            const float2 s1 = unpack2(a1);
            part[(w * BSUB + b) * 32 + lane] = make_float2(s0.x + s1.x, s0.y + s1.y);
        }
        __syncthreads();

        // ---- reduce 16 warp-partials, tanh, write h_{t+1} ----
        float sx = 0.0f, sy = 0.0f;
        #pragma unroll
        for (int ww = 0; ww < NWARPS; ++ww) {
            const float2 p = part[(ww * BSUB + w) * 32 + lane];
            sx += p.x; sy += p.y;
        }
        const float hval = tanhf(sx + sy + bias);
        g_h[(t + 1) & 1][oidx] = hval;
        if (t == T_STEPS - 1) out[oidx] = hval;   // final state -> d_out directly
    }
}

extern "C" void kernel_launch(void* const* d_in, const int* in_sizes, int n_in,
                              void* d_out, int out_size) {
    (void)in_sizes; (void)n_in; (void)out_size;
    const float* x   = (const float*)d_in[0];
    const float* wih = (const float*)d_in[1];
    const float* whh = (const float*)d_in[2];
    const float* bih = (const float*)d_in[3];
    const float* bhh = (const float*)d_in[4];

    cudaFuncSetAttribute(esn_kernel,
                         cudaFuncAttributeMaxDynamicSharedMemorySize, SMEM_BYTES);
    esn_kernel<<<GRID, NTHREADS, SMEM_BYTES>>>(x, wih, whh, bih, bhh, (float*)d_out);
}

// round 15
// speedup vs baseline: 1.0312x; 1.0312x over previous
#include <cuda_runtime.h>
#include <cstdint>

// Problem constants
#define T_STEPS  4096
#define NB       64          // batch
#define NI       128         // input dim
#define NH       1024        // hidden dim
#define KP       1152        // NH + NI (concatenated [h ; x] dot length)
#define GRID     128         // 32 j-blocks x 4 b-blocks (<= 148 SMs, 1 CTA/SM)
#define NTHREADS 512
#define NWARPS   16
#define WPAIRS   36          // (KP/2) / NWARPS : f32x2 pairs per warp-slice
#define WQUADS   18          // 16-byte quads per warp-slice (2 pairs each)
#define BSUB     16          // batches per CTA
#define NJ       32          // output columns per CTA
#define SMEM_BYTES (BSUB * KP * 4 + NWARPS * BSUB * 32 * 8)  // 73728 + 65536 = 139264

// Persistent scratch (no allocation allowed): ping-pong hidden state
__device__ float    g_h[2][NB * NH];
__device__ unsigned g_bar_cnt = 0;
__device__ unsigned g_bar_gen = 0;

__device__ __forceinline__ void fma2(unsigned long long& d,
                                     unsigned long long a,
                                     unsigned long long b) {
    asm("fma.rn.f32x2 %0, %1, %2, %0;" : "+l"(d) : "l"(a), "l"(b));
}
__device__ __forceinline__ unsigned long long pack2(float x, float y) {
    unsigned long long v;
    asm("mov.b64 %0, {%1, %2};" : "=l"(v) : "f"(x), "f"(y));
    return v;
}
__device__ __forceinline__ float2 unpack2(unsigned long long v) {
    float2 f;
    asm("mov.b64 {%0, %1}, %2;" : "=f"(f.x), "=f"(f.y) : "l"(v));
    return f;
}
// 16-byte shared load (two f32x2 pairs in one LDS.128)
__device__ __forceinline__ void lds128(unsigned long long& a, unsigned long long& b,
                                       const void* smem_ptr) {
    asm volatile("ld.shared.v2.u64 {%0, %1}, [%2];"
                 : "=l"(a), "=l"(b)
                 : "l"(__cvta_generic_to_shared(smem_ptr)));
}

// Replay-safe grid barrier. Barrier i releases by setting g_bar_gen = expect
// (= i+1, values cycle 1..T each run; pre-release value is always != expect,
// counter self-resets, so CUDA-graph replays start clean).
__device__ __forceinline__ void grid_barrier(unsigned expect) {
    __threadfence();           // publish this thread's global writes
    __syncthreads();
    if (threadIdx.x == 0) {
        unsigned a = atomicAdd(&g_bar_cnt, 1u);
        if (a == GRID - 1) {
            g_bar_cnt = 0;
            __threadfence();
            atomicExch(&g_bar_gen, expect);
        } else {
            volatile unsigned* gp = &g_bar_gen;
            while (*gp != expect) { __nanosleep(32); }
        }
    }
    __syncthreads();
}

__global__ void __launch_bounds__(NTHREADS, 1)
esn_kernel(const float* __restrict__ x,      // [T, B, I]
           const float* __restrict__ wih,    // [H, I]
           const float* __restrict__ whh,    // [H, H]
           const float* __restrict__ bih,    // [H]
           const float* __restrict__ bhh,    // [H]
           float* __restrict__ out)          // [B, H]
{
    extern __shared__ float smem[];
    float*  hx   = smem;                              // [BSUB][KP]  staged [h ; x_t]
    float2* part = (float2*)(smem + BSUB * KP);       // [NWARPS][BSUB][32] partials

    const int tid  = threadIdx.x;
    const int w    = tid >> 5;                        // warp id (= batch idx in reduce)
    const int lane = tid & 31;                        // = local j
    const int jb   = blockIdx.x & 31;                 // j-block
    const int bb   = blockIdx.x >> 5;                 // b-block
    const int j    = jb * NJ + lane;                  // this lane's output column
    const int b0   = bb * BSUB;

    // ---- persistent packed weights: warp w owns K'-pairs [w*36, w*36+36) ----
    // Concatenated weight row: [ Whh[j, 0..1023] ; Wih[j, 0..127] ]
    unsigned long long Wr[WPAIRS];
    {
        const int kbase = w * (2 * WPAIRS);           // = w*72 (even, 16B aligned)
        #pragma unroll
        for (int r = 0; r < WPAIRS; ++r) {
            const int k = kbase + 2 * r;
            float a, b;
            if (k < NH) { a = whh[j * NH + k];        b = whh[j * NH + k + 1]; }
            else        { a = wih[j * NI + (k - NH)]; b = wih[j * NI + (k - NH) + 1]; }
            Wr[r] = pack2(a, b);
        }
    }

    const float bias = bih[j] + bhh[j];
    const int   oidx = (b0 + w) * NH + j;   // output element owned in reduce phase

    // h_0 = 0 : each CTA zeros exactly its own output block (replay-safe)
    g_h[0][oidx] = 0.0f;

    for (int t = 0; t < T_STEPS; ++t) {
        grid_barrier((unsigned)(t + 1));     // makes h_t (or the zeros) visible

        // ---- stage h_t (L2, bypass stale L1 via ldcg) and x_t into smem ----
        const float* hsrc = g_h[t & 1] + b0 * NH;
        const float* xsrc = x + ((size_t)t * (NB * NI)) + b0 * NI;
        #pragma unroll
        for (int it = 0; it < 9; ++it) {     // 16*288 float4 = 18432 floats
            const int v  = tid + it * NTHREADS;
            const int b  = v / 288;
            const int c4 = v - b * 288;
            float4 val;
            if (c4 < 256) val = __ldcg(((const float4*)(hsrc + b * NH)) + c4);
            else          val = __ldg (((const float4*)(xsrc + b * NI)) + (c4 - 256));
            *(float4*)(hx + b * KP + c4 * 4) = val;
        }
        __syncthreads();

        // ---- partial dot products: LDS.128 broadcast (2 pairs/load),
        //      f32x2 FMA, 4 accumulator chains for ILP ----
        #pragma unroll 1
        for (int b = 0; b < BSUB; ++b) {
            const float* hp = hx + b * KP + w * (2 * WPAIRS);  // 16B aligned
            unsigned long long a0 = 0ull, a1 = 0ull, a2 = 0ull, a3 = 0ull;
            #pragma unroll
            for (int q = 0; q < WQUADS; q += 2) {
                unsigned long long h0, h1, h2, h3;
                lds128(h0, h1, hp + 4 * q);
                lds128(h2, h3, hp + 4 * q + 4);
                fma2(a0, h0, Wr[2 * q]);
                fma2(a1, h1, Wr[2 * q + 1]);
                fma2(a2, h2, Wr[2 * q + 2]);
                fma2(a3, h3, Wr[2 * q + 3]);
            }
            const float2 s0 = unpack2(a0);
            const float2 s1 = unpack2(a1);
            const float2 s2 = unpack2(a2);
            const float2 s3 = unpack2(a3);
            part[(w * BSUB + b) * 32 + lane] =
                make_float2((s0.x + s1.x) + (s2.x + s3.x),
                            (s0.y + s1.y) + (s2.y + s3.y));
        }
        __syncthreads();

        // ---- reduce 16 warp-partials, tanh, write h_{t+1} ----
        float sx = 0.0f, sy = 0.0f;
        #pragma unroll
        for (int ww = 0; ww < NWARPS; ++ww) {
            const float2 p = part[(ww * BSUB + w) * 32 + lane];
            sx += p.x; sy += p.y;
        }
        const float hval = tanhf(sx + sy + bias);
        g_h[(t + 1) & 1][oidx] = hval;
        if (t == T_STEPS - 1) out[oidx] = hval;   // final state -> d_out directly
    }
}

extern "C" void kernel_launch(void* const* d_in, const int* in_sizes, int n_in,
                              void* d_out, int out_size) {
    (void)in_sizes; (void)n_in; (void)out_size;
    const float* x   = (const float*)d_in[0];
    const float* wih = (const float*)d_in[1];
    const float* whh = (const float*)d_in[2];
    const float* bih = (const float*)d_in[3];
    const float* bhh = (const float*)d_in[4];

    cudaFuncSetAttribute(esn_kernel,
                         cudaFuncAttributeMaxDynamicSharedMemorySize, SMEM_BYTES);
    esn_kernel<<<GRID, NTHREADS, SMEM_BYTES>>>(x, wih, whh, bih, bhh, (float*)d_out);
}

// round 17
// speedup vs baseline: 1.2326x; 1.1952x over previous
#include <cuda_runtime.h>
#include <cstdint>

// Problem constants
#define T_STEPS  4096
#define NB       64          // batch
#define NI       128         // input dim
#define NH       1024        // hidden dim
#define KP       1152        // NH + NI (concatenated [h ; x] dot length)
#define GRID     128         // 32 j-blocks x 4 b-blocks (1 CTA/SM on 148 SMs)
#define NTHREADS 512
#define NWARPS   16
#define BSUB     16          // batches per CTA
#define NJ       32          // output columns per CTA
#define NSLICES  32          // K' split into 32 subslices
#define SPAIRS   18          // f32x2 pairs per subslice (36 floats)
#define SMEM_BYTES (BSUB * KP * 4 + NSLICES * BSUB * 16 * 8)  // 73728 + 65536 = 139264

// Persistent scratch: ping-pong hidden state + per-batch-group barriers
__device__ float    g_h[2][NB * NH];
__device__ unsigned g_bar_cnt[4 * 32];   // one counter per bb-group, padded 128B
__device__ unsigned g_bar_gen[4 * 32];

__device__ __forceinline__ void fma2(unsigned long long& d,
                                     unsigned long long a,
                                     unsigned long long b) {
    asm("fma.rn.f32x2 %0, %1, %2, %0;" : "+l"(d) : "l"(a), "l"(b));
}
__device__ __forceinline__ unsigned long long pack2(float x, float y) {
    unsigned long long v;
    asm("mov.b64 %0, {%1, %2};" : "=l"(v) : "f"(x), "f"(y));
    return v;
}
__device__ __forceinline__ float fold2(unsigned long long v) {
    float fx, fy;
    asm("mov.b64 {%0, %1}, %2;" : "=f"(fx), "=f"(fy) : "l"(v));
    return fx + fy;
}
// 16-byte shared load (two f32x2 pairs)
__device__ __forceinline__ void lds128(unsigned long long& a, unsigned long long& b,
                                       const void* smem_ptr) {
    asm volatile("ld.shared.v2.u64 {%0, %1}, [%2];"
                 : "=l"(a), "=l"(b)
                 : "l"(__cvta_generic_to_shared(smem_ptr)));
}

// Replay-safe 32-CTA barrier (one group per batch-block). Barrier i releases
// by setting gen = expect (cycles 1..T, pre-release value always != expect,
// counter self-resets -> clean under CUDA-graph replay).
__device__ __forceinline__ void group_barrier(int grp, unsigned expect) {
    __threadfence();           // publish this CTA's g_h writes
    __syncthreads();
    if (threadIdx.x == 0) {
        unsigned a = atomicAdd(&g_bar_cnt[grp * 32], 1u);
        if (a == 31) {
            g_bar_cnt[grp * 32] = 0;
            __threadfence();
            atomicExch(&g_bar_gen[grp * 32], expect);
        } else {
            volatile unsigned* gp = &g_bar_gen[grp * 32];
            while (*gp != expect) { __nanosleep(20); }
        }
    }
    __syncthreads();
}

__global__ void __launch_bounds__(NTHREADS, 1)
esn_kernel(const float* __restrict__ x,      // [T, B, I]
           const float* __restrict__ wih,    // [H, I]
           const float* __restrict__ whh,    // [H, H]
           const float* __restrict__ bih,    // [H]
           const float* __restrict__ bhh,    // [H]
           float* __restrict__ out)          // [B, H]
{
    extern __shared__ float smem[];
    float*  hx   = smem;                              // [BSUB][KP]  staged [h ; x_t]
    float2* part = (float2*)(smem + BSUB * KP);       // [NSLICES][BSUB][16] (j-pair partials)

    const int tid  = threadIdx.x;
    const int w    = tid >> 5;
    const int lane = tid & 31;
    const int jb   = blockIdx.x & 31;                 // j-block
    const int bb   = blockIdx.x >> 5;                 // b-block (barrier group)
    const int b0   = bb * BSUB;

    // compute-phase identity: lane owns K-subslice `slice` and 2 columns j0,j0+1
    const int p15   = lane & 15;
    const int g     = lane >> 4;
    const int slice = w * 2 + g;                      // 0..31
    const int kbase = slice * (2 * SPAIRS);           // float offset in K' (=slice*36)
    const int j0    = jb * NJ + 2 * p15;

    // ---- persistent packed weights: 18 pairs x 2 columns = 72 regs ----
    // Concatenated weight row: [ Whh[j, 0..1023] ; Wih[j, 0..127] ]
    unsigned long long W0[SPAIRS], W1[SPAIRS];
    #pragma unroll
    for (int r = 0; r < SPAIRS; ++r) {
        const int k = kbase + 2 * r;
        float a0, b0f, a1, b1f;
        if (k < NH) {
            a0 = whh[j0 * NH + k];              b0f = whh[j0 * NH + k + 1];
            a1 = whh[(j0 + 1) * NH + k];        b1f = whh[(j0 + 1) * NH + k + 1];
        } else {
            a0 = wih[j0 * NI + (k - NH)];       b0f = wih[j0 * NI + (k - NH) + 1];
            a1 = wih[(j0 + 1) * NI + (k - NH)]; b1f = wih[(j0 + 1) * NI + (k - NH) + 1];
        }
        W0[r] = pack2(a0, b0f);
        W1[r] = pack2(a1, b1f);
    }

    // reduce-phase identity: thread (w = batch, lane = j)
    const int   jr   = jb * NJ + lane;
    const float bias = bih[jr] + bhh[jr];
    const int   oidx = (b0 + w) * NH + jr;

    // h_0 = 0 : each CTA zeros exactly its own output block (replay-safe)
    g_h[0][oidx] = 0.0f;

    // pre-stage x_0 into the x-part of hx (1 float4 per thread)
    {
        const float* xsrc = x + b0 * NI;
        const int b  = tid >> 5;       // 16 rows
        const int c4 = tid & 31;       // 32 float4 per row
        float4 val = __ldg(((const float4*)(xsrc + b * NI)) + c4);
        *(float4*)(hx + b * KP + NH + c4 * 4) = val;
    }

    for (int t = 0; t < T_STEPS; ++t) {
        group_barrier(bb, (unsigned)(t + 1));   // makes h_t (or zeros) visible

        // ---- stage h_t only (x already staged): 4096 float4, 8 per thread ----
        const float* hsrc = g_h[t & 1] + b0 * NH;
        #pragma unroll
        for (int it = 0; it < 8; ++it) {
            const int v  = tid + it * NTHREADS;
            const int b  = v >> 8;              // 256 float4 per h-row
            const int c4 = v & 255;
            float4 val = __ldcg(((const float4*)(hsrc + b * NH)) + c4);
            *(float4*)(hx + b * KP + c4 * 4) = val;
        }
        __syncthreads();

        // ---- partials: each 16B h-load feeds 4 FFMA2 (2 pairs x 2 columns) ----
        #pragma unroll 1
        for (int b = 0; b < BSUB; ++b) {
            const float* hp = hx + b * KP + kbase;   // 16B aligned (144B per slice)
            unsigned long long a00 = 0ull, a01 = 0ull, a10 = 0ull, a11 = 0ull;
            #pragma unroll
            for (int r = 0; r < SPAIRS / 2; ++r) {   // 9 x LDS.128, 4 floats each
                unsigned long long hA, hB;
                lds128(hA, hB, hp + 4 * r);          // <-- fixed stride (was 8*r)
                fma2(a00, hA, W0[2 * r]);
                fma2(a10, hA, W1[2 * r]);
                fma2(a01, hB, W0[2 * r + 1]);
                fma2(a11, hB, W1[2 * r + 1]);
            }
            float2 f;
            f.x = fold2(a00) + fold2(a01);   // partial for j0
            f.y = fold2(a10) + fold2(a11);   // partial for j0+1
            part[(slice * BSUB + b) * 16 + p15] = f;
        }
        __syncthreads();

        // ---- prefetch x_{t+1} (independent of h, hides gmem latency) ----
        if (t + 1 < T_STEPS) {
            const float* xsrc = x + ((size_t)(t + 1) * (NB * NI)) + b0 * NI;
            const int b  = tid >> 5;
            const int c4 = tid & 31;
            float4 val = __ldg(((const float4*)(xsrc + b * NI)) + c4);
            *(float4*)(hx + b * KP + NH + c4 * 4) = val;
        }

        // ---- reduce 32 slice-partials, tanh, write h_{t+1} ----
        float s0 = 0.0f, s1 = 0.0f;
        #pragma unroll
        for (int ss = 0; ss < NSLICES; ss += 2) {
            const float2 v0 = part[(ss * BSUB + w) * 16 + (lane >> 1)];
            const float2 v1 = part[((ss + 1) * BSUB + w) * 16 + (lane >> 1)];
            s0 += (lane & 1) ? v0.y : v0.x;
            s1 += (lane & 1) ? v1.y : v1.x;
        }
        const float hval = tanhf(s0 + s1 + bias);
        g_h[(t + 1) & 1][oidx] = hval;
        if (t == T_STEPS - 1) out[oidx] = hval;   // final state -> d_out
    }
}

extern "C" void kernel_launch(void* const* d_in, const int* in_sizes, int n_in,
                              void* d_out, int out_size) {
    (void)in_sizes; (void)n_in; (void)out_size;
    const float* x   = (const float*)d_in[0];
    const float* wih = (const float*)d_in[1];
    const float* whh = (const float*)d_in[2];
    const float* bih = (const float*)d_in[3];
    const float* bhh = (const float*)d_in[4];

    cudaFuncSetAttribute(esn_kernel,
                         cudaFuncAttributeMaxDynamicSharedMemorySize, SMEM_BYTES);
    esn_kernel<<<GRID, NTHREADS, SMEM_BYTES>>>(x, wih, whh, bih, bhh, (float*)d_out);
}